// round 8
// baseline (speedup 1.0000x reference)
#include <cuda_runtime.h>
#include <math.h>

#define BATCH 1024
#define CH 32
#define LIN 1024
#define LCONV 1041
#define LH 520

typedef unsigned long long ull;

// ---------------- scratch (device globals; no allocation) ----------------
__device__ float g_filt[CH * 16];
__device__ float g_xpart[BATCH * 17];     // per-row partial: lags 0..15, row-sum at 16
__device__ float g_bn1_sc3[CH];
__device__ float g_bn1_sh[CH];
__device__ float g_x1pre[BATCH * CH * 31];
__device__ float g_x2pre[BATCH * CH * 31];
__device__ float g_p2s[BATCH * CH];
__device__ float g_p2q[BATCH * CH];
__device__ float g_p3s[BATCH * CH];
__device__ float g_p3q[BATCH * CH];
__device__ float g_bn2_sc[CH], g_bn2_sh[CH], g_bn3_sc[CH], g_bn3_sh[CH];
__device__ float g_z[BATCH * 768];
__device__ float g_a1[BATCH * 1024];
__device__ float g_a2[BATCH * 512];

// ---------------- f32x2 helpers (per-lane IEEE fp32; verified bit-identical R7) ----------------
__device__ __forceinline__ void ffma2(ull& d, ull a, ull b) {
    asm("fma.rn.f32x2 %0, %1, %2, %0;" : "+l"(d) : "l"(a), "l"(b));
}
__device__ __forceinline__ ull pack2(float lo, float hi) {
    ull r; asm("mov.b64 %0, {%1, %2};" : "=l"(r) : "f"(lo), "f"(hi)); return r;
}
__device__ __forceinline__ void unpack2(float& lo, float& hi, ull v) {
    asm("mov.b64 {%0, %1}, %2;" : "=f"(lo), "=f"(hi) : "l"(v));
}

// ---------------- x row statistics (+ filter bank computed by block 0) ----------------
__global__ __launch_bounds__(256) void k_xstats(const float* __restrict__ x,
                                                const float* __restrict__ la_a,
                                                const float* __restrict__ la_b) {
    __shared__ __align__(16) float xs[LIN + 16];
    __shared__ float part[8][17];
    int b = blockIdx.x, tid = threadIdx.x;
    int warp = tid >> 5, lane = tid & 31;

    if (b == 0) {  // filter bank: consumers run in later kernels
        for (int idx = tid; idx < CH * 16; idx += 256) {
            int c = idx >> 4, k = idx & 15;
            const double A = 0.08, ep = 0.03, tal = 0.1;
            const double w = 6.283185307179586 * 50.0;
            const double coef = -ep / sqrt(1.0 - ep * ep);
            double ratio = (double)la_b[c] / (double)la_a[c];
            double t = (double)k / 15.0;
            double arg = w * (t - ratio - tal);
            g_filt[c * 16 + k] = (float)(A * exp(coef * arg) * (-sin(arg)));
        }
    }

    for (int i = tid; i < LIN + 16; i += 256)
        xs[i] = (i < LIN) ? x[b * LIN + i] : 0.f;
    __syncthreads();
    float r[20];
    {
        const float4* p4 = (const float4*)&xs[4 * tid];
#pragma unroll
        for (int w = 0; w < 5; w++) {
            float4 q = p4[w];
            r[4 * w] = q.x; r[4 * w + 1] = q.y; r[4 * w + 2] = q.z; r[4 * w + 3] = q.w;
        }
    }
    float acc[16];
#pragma unroll
    for (int d = 0; d < 16; d++) acc[d] = 0.f;
    float s = 0.f;
#pragma unroll
    for (int j = 0; j < 4; j++) {
        float xi = r[j];
        s += xi;
#pragma unroll
        for (int d = 0; d < 16; d++) acc[d] = fmaf(xi, r[j + d], acc[d]);
    }
#pragma unroll
    for (int off = 16; off > 0; off >>= 1) {
        s += __shfl_down_sync(0xffffffffu, s, off);
#pragma unroll
        for (int d = 0; d < 16; d++)
            acc[d] += __shfl_down_sync(0xffffffffu, acc[d], off);
    }
    if (lane == 0) {
#pragma unroll
        for (int d = 0; d < 16; d++) part[warp][d] = acc[d];
        part[warp][16] = s;
    }
    __syncthreads();
    if (tid < 17) {
        float t = 0.f;
#pragma unroll
        for (int w = 0; w < 8; w++) t += part[w][tid];
        g_xpart[b * 17 + tid] = t;
    }
}

// ---------------- fused reduction + BN1 affine (single block, 544 threads) ----------------
__global__ __launch_bounds__(544) void k_redbn1(const float* __restrict__ la_bias,
                                                const float* __restrict__ g1,
                                                const float* __restrict__ b1) {
    __shared__ double Rs[17];
    int tid = threadIdx.x, warp = tid >> 5, lane = tid & 31;
    if (warp < 17) {
        double s = 0;
        for (int b = lane; b < BATCH; b += 32) s += (double)g_xpart[b * 17 + warp];
#pragma unroll
        for (int off = 16; off > 0; off >>= 1)
            s += __shfl_down_sync(0xffffffffu, s, off);
        if (lane == 0) Rs[warp] = s;
    }
    __syncthreads();
    if (tid < CH * 16) {
        int c = tid >> 4, k = tid & 15;
        double fk = (double)g_filt[c * 16 + k];
        double q = 0;
#pragma unroll
        for (int k2 = 0; k2 < 16; k2++) {
            int d = k2 - k; if (d < 0) d = -d;
            q += (double)g_filt[c * 16 + k2] * Rs[d];
        }
        q *= fk;
        double F1p = fk;
#pragma unroll
        for (int off = 8; off > 0; off >>= 1) {
            q += __shfl_down_sync(0xffffffffu, q, off, 16);
            F1p += __shfl_down_sync(0xffffffffu, F1p, off, 16);
        }
        if (k == 0) {
            double S = Rs[16];
            double N = (double)BATCH * (double)LCONV;
            double Ey = F1p * S / N;
            double var = q / N - Ey * Ey;
            double mean = (double)la_bias[c] + Ey;
            double inv = 1.0 / sqrt(var + 1e-5);
            double sc = (double)g1[c] * inv;
            g_bn1_sc3[c] = (float)(sc / 3.0);
            g_bn1_sh[c] = (float)((double)b1[c] - mean * sc);
        }
    }
}

// ---------------- pass 2: fused conv+BN+avgpool -> register-resident branches ----------------
#define HPAD 556
__global__ __launch_bounds__(256) void k_branch(
    const float* __restrict__ x, const float* __restrict__ la_bias,
    const float* __restrict__ a1_w, const float* __restrict__ a1_b,
    const float* __restrict__ e1_w, const float* __restrict__ e1_b,
    const float* __restrict__ f1_w, const float* __restrict__ f1_b,
    const float* __restrict__ fa_w, const float* __restrict__ fa_b) {
    __shared__ __align__(16) float xsg[130 * 28];
    __shared__ float hw[8][HPAD];
    int b = blockIdx.x, tid = threadIdx.x;
    int warp = tid >> 5, lane = tid & 31;
    const float* xr = x + b * LIN;

    for (int idx = tid; idx < 130 * 24; idx += 256) {
        int g = idx / 24, j = idx - g * 24;
        int pos = 8 * g + j;
        xsg[g * 28 + j] = (pos >= 16 && pos < 16 + LIN) ? xr[pos - 16] : 0.f;
    }
    __syncthreads();

    float* h = hw[warp];

    for (int cg = 0; cg < 4; cg++) {
        int c = warp + 8 * cg;
        float fw[16];
#pragma unroll
        for (int k = 0; k < 16; k++) fw[k] = g_filt[c * 16 + k];
        float cw[18];
#pragma unroll
        for (int j = 0; j < 18; j++) {
            float s = 0.f;
#pragma unroll
            for (int p = 0; p < 3; p++) {
                int k = j - p;
                if (k >= 0 && k < 16) s += fw[k];
            }
            cw[j] = s;
        }
        float sc3 = g_bn1_sc3[c];
        float sh2 = fmaf(3.f * la_bias[c], sc3, g_bn1_sh[c]);

        for (int g = lane; g < 130; g += 32) {
            const float4* p4 = (const float4*)&xsg[g * 28];
            float r[24];
#pragma unroll
            for (int w = 0; w < 6; w++) {
                float4 q = p4[w];
                r[4 * w] = q.x; r[4 * w + 1] = q.y; r[4 * w + 2] = q.z; r[4 * w + 3] = q.w;
            }
            int base = 4 * g + (g >> 2);
#pragma unroll
            for (int d = 0; d < 4; d++) {
                float s = 0.f;
#pragma unroll
                for (int j = 0; j < 18; j++) s = fmaf(r[2 * d + j], cw[j], s);
                h[base + d] = fmaf(s, sc3, sh2);
            }
        }
        __syncwarp();

        float mvA = 0.f, mvB = 0.f;
        if (lane < 31) {
            int hb = 17 * lane;
            float hr[34];
#pragma unroll
            for (int j = 0; j < 34; j++) hr[j] = h[hb + j + (j >> 4)];

            {
                float w8[8];
#pragma unroll
                for (int k = 0; k < 8; k++) w8[k] = a1_w[c * 8 + k];
                float wsum = 0.f;
#pragma unroll
                for (int k = 0; k < 8; k++) wsum += w8[k];
                float wbA = a1_b[c] - wsum;
                float ua[14];
#pragma unroll
                for (int i = 0; i < 14; i++) {
                    float a = wbA;
#pragma unroll
                    for (int k = 0; k < 8; k++) a = fmaf(hr[2 * i + k], w8[k], a);
                    ua[i] = fmaxf(a, 0.f);
                }
                float wE[8];
#pragma unroll
                for (int k = 0; k < 8; k++) wE[k] = e1_w[c * 8 + k];
                float wbE = 1.f - e1_b[c];
#pragma unroll
                for (int j = 0; j < 4; j++) {
                    float a = wbE;
#pragma unroll
                    for (int k = 0; k < 8; k++) a = fmaf(ua[2 * j + k], wE[k], a);
                    mvA = fmaxf(mvA, a);
                }
                g_x1pre[(b * CH + c) * 31 + lane] = mvA;
            }
            {
                float w8[8];
#pragma unroll
                for (int k = 0; k < 8; k++) w8[k] = f1_w[c * 8 + k];
                float wbF = 1.f - f1_b[c];
                float ub[14];
#pragma unroll
                for (int i = 0; i < 14; i++) {
                    float a = wbF;
#pragma unroll
                    for (int k = 0; k < 8; k++) a = fmaf(hr[2 * i + k], w8[k], a);
                    ub[i] = fmaxf(a, 0.f);
                }
                float wA[8];
#pragma unroll
                for (int k = 0; k < 8; k++) wA[k] = fa_w[c * 8 + k];
                float wsum = 0.f;
#pragma unroll
                for (int k = 0; k < 8; k++) wsum += wA[k];
                float wbA2 = fa_b[c] - wsum;
#pragma unroll
                for (int j = 0; j < 4; j++) {
                    float a = wbA2;
#pragma unroll
                    for (int k = 0; k < 8; k++) a = fmaf(ub[2 * j + k], wA[k], a);
                    mvB = fmaxf(mvB, a);
                }
                g_x2pre[(b * CH + c) * 31 + lane] = mvB;
            }
        }
        float sA = mvA, qA = mvA * mvA, sB = mvB, qB = mvB * mvB;
#pragma unroll
        for (int off = 16; off > 0; off >>= 1) {
            sA += __shfl_down_sync(0xffffffffu, sA, off);
            qA += __shfl_down_sync(0xffffffffu, qA, off);
            sB += __shfl_down_sync(0xffffffffu, sB, off);
            qB += __shfl_down_sync(0xffffffffu, qB, off);
        }
        if (lane == 0) {
            g_p2s[b * CH + c] = sA; g_p2q[b * CH + c] = qA;
            g_p3s[b * CH + c] = sB; g_p3q[b * CH + c] = qB;
        }
        __syncwarp();
    }
}

// ---------------- finalize BN2 / BN3 affine ----------------
__global__ void k_bn23(const float* __restrict__ g2, const float* __restrict__ b2,
                       const float* __restrict__ g3, const float* __restrict__ b3) {
    int c = blockIdx.x, which = blockIdx.y, tid = threadIdx.x;
    const float* ps = which ? g_p3s : g_p2s;
    const float* pq = which ? g_p3q : g_p2q;
    __shared__ double ss[128], sq[128];
    double s = 0, q = 0;
    for (int b = tid; b < BATCH; b += 128) {
        s += (double)ps[b * CH + c];
        q += (double)pq[b * CH + c];
    }
    ss[tid] = s; sq[tid] = q; __syncthreads();
    for (int o = 64; o > 0; o >>= 1) {
        if (tid < o) { ss[tid] += ss[tid + o]; sq[tid] += sq[tid + o]; }
        __syncthreads();
    }
    if (tid == 0) {
        double N = (double)BATCH * 31.0;
        double mean = ss[0] / N;
        double var = sq[0] / N - mean * mean;
        double inv = 1.0 / sqrt(var + 1e-5);
        double gg = which ? (double)g3[c] : (double)g2[c];
        double bb = which ? (double)b3[c] : (double)b2[c];
        double sc = gg * inv;
        if (which) { g_bn3_sc[c] = (float)sc; g_bn3_sh[c] = (float)(bb - mean * sc); }
        else       { g_bn2_sc[c] = (float)sc; g_bn2_sh[c] = (float)(bb - mean * sc); }
    }
}

// ---------------- BN + final eventually conv -> concat features z (B,768) ----------------
__global__ __launch_bounds__(128) void k_final(const float* __restrict__ e2_w,
                                               const float* __restrict__ e2_b,
                                               const float* __restrict__ f2_w,
                                               const float* __restrict__ f2_b) {
    int b = blockIdx.x;
    for (int idx = threadIdx.x; idx < 768; idx += 128) {
        int ct = idx / 12, j = idx % 12;
        int c = ct & 31;
        bool second = ct >= 32;
        const float* pre = (second ? g_x2pre : g_x1pre) + (b * CH + c) * 31 + 2 * j;
        const float* w = (second ? f2_w : e2_w) + c * 8;
        float base = 1.f - (second ? f2_b[c] : e2_b[c]);
        float sc = second ? g_bn3_sc[c] : g_bn2_sc[c];
        float shv = second ? g_bn3_sh[c] : g_bn2_sh[c];
        float sw = 0.f, dot = 0.f;
#pragma unroll
        for (int k = 0; k < 8; k++) { sw += w[k]; dot = fmaf(pre[k], w[k], dot); }
        float val = base + shv * sw + sc * dot;
        g_z[b * 768 + idx] = fmaxf(val, 0.f);
    }
}

// ---------------- SGEMM: R4-proven geometry (BM=64, BK=8, 64 thr, 8x8) + f32x2 inner ----------------
__global__ __launch_bounds__(64) void gemm_f2(const float* __restrict__ A,
                                              const float* __restrict__ B,
                                              const float* __restrict__ bias,
                                              float* __restrict__ C,
                                              int M, int N, int K) {
    constexpr int BM = 64, BK = 8, TM = 8, TNH = 4, LPT = 2;
    const int tid = threadIdx.x;
    const int tx = tid & 7;
    const int ty = tid >> 3;
    const int m0 = blockIdx.y * BM;
    const int n0 = blockIdx.x * BM;
    __shared__ __align__(16) float As[BK][BM];
    __shared__ __align__(16) float Bs[BK][BM];
    ull acc[TM][TNH];
#pragma unroll
    for (int i = 0; i < TM; i++)
#pragma unroll
        for (int p = 0; p < TNH; p++) acc[i][p] = 0ULL;

    float4 pa[LPT], pb[LPT];
    const int nt = K / BK;

    auto loadG = [&](int t) {
        int k0 = t * BK;
#pragma unroll
        for (int L = 0; L < LPT; L++) {
            int i = tid + L * 64;
            int ar = i >> 1, ag = i & 1;
            pa[L] = *(const float4*)(A + (size_t)(m0 + ar) * K + k0 + ag * 4);
            int bk = i >> 4, bc = i & 15;
            pb[L] = *(const float4*)(B + (size_t)(k0 + bk) * N + n0 + bc * 4);
        }
    };
    auto storeS = [&]() {
#pragma unroll
        for (int L = 0; L < LPT; L++) {
            int i = tid + L * 64;
            int ar = i >> 1, ag = i & 1;
            As[ag * 4 + 0][ar] = pa[L].x; As[ag * 4 + 1][ar] = pa[L].y;
            As[ag * 4 + 2][ar] = pa[L].z; As[ag * 4 + 3][ar] = pa[L].w;
            int bk = i >> 4, bc = i & 15;
            *(float4*)(&Bs[bk][bc * 4]) = pb[L];
        }
    };

    loadG(0); storeS(); __syncthreads();
    for (int t = 0; t < nt; t++) {
        if (t + 1 < nt) loadG(t + 1);
#pragma unroll
        for (int kk = 0; kk < BK; kk++) {
            float af[TM];
#pragma unroll
            for (int i = 0; i < TM; i += 4) {
                float4 qa = *(const float4*)(&As[kk][ty * TM + i]);
                af[i] = qa.x; af[i + 1] = qa.y; af[i + 2] = qa.z; af[i + 3] = qa.w;
            }
            ull bf[TNH];
#pragma unroll
            for (int p = 0; p < TNH; p++)
                bf[p] = *(const ull*)(&Bs[kk][tx * TM + 2 * p]);
            ull ad[TM];
#pragma unroll
            for (int i = 0; i < TM; i++) ad[i] = pack2(af[i], af[i]);
#pragma unroll
            for (int i = 0; i < TM; i++)
#pragma unroll
                for (int p = 0; p < TNH; p++) ffma2(acc[i][p], ad[i], bf[p]);
        }
        __syncthreads();
        if (t + 1 < nt) { storeS(); __syncthreads(); }
    }
#pragma unroll
    for (int i = 0; i < TM; i++) {
        int m = m0 + ty * TM + i;
        float o[TM];
#pragma unroll
        for (int p = 0; p < TNH; p++) unpack2(o[2 * p], o[2 * p + 1], acc[i][p]);
#pragma unroll
        for (int j = 0; j < TM; j += 4) {
            int n = n0 + tx * TM + j;
            float4 r;
            r.x = fmaxf(o[j] + bias[n], 0.f);
            r.y = fmaxf(o[j + 1] + bias[n + 1], 0.f);
            r.z = fmaxf(o[j + 2] + bias[n + 2], 0.f);
            r.w = fmaxf(o[j + 3] + bias[n + 3], 0.f);
            *(float4*)(C + (size_t)m * N + n) = r;
        }
    }
}

// ---------------- GEMM3 (1024x128x512) fused with FC4 epilogue -> out (B,10) ----------------
// 32x128 tiles (full N per block) so fc4 is row-local. 128 threads.
__global__ __launch_bounds__(128) void gemm3_fc4(const float* __restrict__ A,
                                                 const float* __restrict__ B,
                                                 const float* __restrict__ bias,
                                                 const float* __restrict__ w4,
                                                 const float* __restrict__ b4,
                                                 float* __restrict__ out) {
    constexpr int BM = 32, BN = 128, BK = 16, TM = 4, TN = 8;
    constexpr int K = 512, N = 128;
    const int tid = threadIdx.x;
    const int tx = tid & 15;   // 16 col groups * TN=8 -> 128
    const int ty = tid >> 4;   // 8 row groups * TM=4 -> 32
    const int m0 = blockIdx.x * BM;
    __shared__ __align__(16) float As[BK][BM];
    __shared__ __align__(16) float Bs[BK][BN];
    __shared__ float a3s[BM][BN + 1];
    __shared__ float w4s[128 * 10];

    for (int i = tid; i < 128 * 10; i += 128) w4s[i] = w4[i];

    float acc[TM][TN];
#pragma unroll
    for (int i = 0; i < TM; i++)
#pragma unroll
        for (int j = 0; j < TN; j++) acc[i][j] = 0.f;

    float4 pa, pb[4];
    const int nt = K / BK;
    const int ar = tid >> 2, ac = tid & 3;    // A: 32 rows x 4 col-groups
    auto loadG = [&](int t) {
        int k0 = t * BK;
        pa = *(const float4*)(A + (size_t)(m0 + ar) * K + k0 + ac * 4);
#pragma unroll
        for (int L = 0; L < 4; L++) {
            int i = tid + L * 128;
            int br = i >> 5, bc = i & 31;
            pb[L] = *(const float4*)(B + (size_t)(k0 + br) * N + bc * 4);
        }
    };
    auto storeS = [&]() {
        As[ac * 4 + 0][ar] = pa.x; As[ac * 4 + 1][ar] = pa.y;
        As[ac * 4 + 2][ar] = pa.z; As[ac * 4 + 3][ar] = pa.w;
#pragma unroll
        for (int L = 0; L < 4; L++) {
            int i = tid + L * 128;
            int br = i >> 5, bc = i & 31;
            *(float4*)(&Bs[br][bc * 4]) = pb[L];
        }
    };

    loadG(0); storeS(); __syncthreads();
    for (int t = 0; t < nt; t++) {
        if (t + 1 < nt) loadG(t + 1);
#pragma unroll
        for (int kk = 0; kk < BK; kk++) {
            float4 qa = *(const float4*)(&As[kk][ty * TM]);
            float af[4] = {qa.x, qa.y, qa.z, qa.w};
            float bf[TN];
#pragma unroll
            for (int j = 0; j < TN; j += 4) {
                float4 qb = *(const float4*)(&Bs[kk][tx * TN + j]);
                bf[j] = qb.x; bf[j + 1] = qb.y; bf[j + 2] = qb.z; bf[j + 3] = qb.w;
            }
#pragma unroll
            for (int i = 0; i < TM; i++)
#pragma unroll
                for (int j = 0; j < TN; j++) acc[i][j] = fmaf(af[i], bf[j], acc[i][j]);
        }
        __syncthreads();
        if (t + 1 < nt) { storeS(); __syncthreads(); }
    }
    // relu(acc + bias) -> smem a3 tile
#pragma unroll
    for (int i = 0; i < TM; i++) {
        int m = ty * TM + i;
#pragma unroll
        for (int j = 0; j < TN; j++) {
            int n = tx * TN + j;
            a3s[m][n] = fmaxf(acc[i][j] + bias[n], 0.f);
        }
    }
    __syncthreads();
    // fc4: 32 rows x 10 outputs = 320 over 128 threads
    for (int idx = tid; idx < BM * 10; idx += 128) {
        int m = idx / 10, n = idx - m * 10;
        float a = b4[n];
#pragma unroll 8
        for (int k = 0; k < 128; k++) a = fmaf(a3s[m][k], w4s[k * 10 + n], a);
        out[(m0 + m) * 10 + n] = fmaxf(a, 0.f);
    }
}

// ---------------- launch ----------------
extern "C" void kernel_launch(void* const* d_in, const int* in_sizes, int n_in,
                              void* d_out, int out_size) {
    const float* x       = (const float*)d_in[0];
    const float* la_a    = (const float*)d_in[1];
    const float* la_b    = (const float*)d_in[2];
    const float* la_bias = (const float*)d_in[3];
    const float* bn1_g   = (const float*)d_in[4];
    const float* bn1_b   = (const float*)d_in[5];
    const float* a1_w    = (const float*)d_in[6];
    const float* a1_b    = (const float*)d_in[7];
    const float* e1_w    = (const float*)d_in[8];
    const float* e1_b    = (const float*)d_in[9];
    const float* bn2_g   = (const float*)d_in[10];
    const float* bn2_b   = (const float*)d_in[11];
    const float* e2_w    = (const float*)d_in[12];
    const float* e2_b    = (const float*)d_in[13];
    const float* f1_w    = (const float*)d_in[14];
    const float* f1_b    = (const float*)d_in[15];
    const float* fa_w    = (const float*)d_in[16];
    const float* fa_b    = (const float*)d_in[17];
    const float* bn3_g   = (const float*)d_in[18];
    const float* bn3_b   = (const float*)d_in[19];
    const float* f2_w    = (const float*)d_in[20];
    const float* f2_b    = (const float*)d_in[21];
    const float* w1 = (const float*)d_in[22]; const float* b1 = (const float*)d_in[23];
    const float* w2 = (const float*)d_in[24]; const float* b2 = (const float*)d_in[25];
    const float* w3 = (const float*)d_in[26]; const float* b3 = (const float*)d_in[27];
    const float* w4 = (const float*)d_in[28]; const float* b4 = (const float*)d_in[29];
    float* out = (float*)d_out;

    float *p_z = nullptr, *p_a1 = nullptr, *p_a2 = nullptr;
    cudaGetSymbolAddress((void**)&p_z, g_z);
    cudaGetSymbolAddress((void**)&p_a1, g_a1);
    cudaGetSymbolAddress((void**)&p_a2, g_a2);

    k_xstats<<<BATCH, 256>>>(x, la_a, la_b);
    k_redbn1<<<1, 544>>>(la_bias, bn1_g, bn1_b);
    k_branch<<<BATCH, 256>>>(x, la_bias, a1_w, a1_b, e1_w, e1_b,
                             f1_w, f1_b, fa_w, fa_b);
    k_bn23<<<dim3(CH, 2), 128>>>(bn2_g, bn2_b, bn3_g, bn3_b);
    k_final<<<BATCH, 128>>>(e2_w, e2_b, f2_w, f2_b);
    gemm_f2<<<dim3(16, 16), 64>>>(p_z, w1, b1, p_a1, 1024, 1024, 768);
    gemm_f2<<<dim3(8, 16), 64>>>(p_a1, w2, b2, p_a2, 1024, 512, 1024);
    gemm3_fc4<<<32, 128>>>(p_a2, w3, b3, w4, b4, out);
}

// round 10
// speedup vs baseline: 1.1242x; 1.1242x over previous
#include <cuda_runtime.h>
#include <math.h>

#define BATCH 1024
#define CH 32
#define LIN 1024
#define LCONV 1041
#define LH 520

// ---------------- scratch (device globals; no allocation) ----------------
__device__ float g_filt[CH * 16];
__device__ float g_xpart[BATCH * 17];     // per-row partial: lags 0..15, row-sum at 16
__device__ float g_bn1_sc3[CH];
__device__ float g_bn1_sh[CH];
__device__ float g_x1pre[BATCH * CH * 31];
__device__ float g_x2pre[BATCH * CH * 31];
__device__ float g_p2s[BATCH * CH];
__device__ float g_p2q[BATCH * CH];
__device__ float g_p3s[BATCH * CH];
__device__ float g_p3q[BATCH * CH];
__device__ float g_bn2_sc[CH], g_bn2_sh[CH], g_bn3_sc[CH], g_bn3_sh[CH];
__device__ float g_z[BATCH * 768];
__device__ float g_a1[BATCH * 1024];
__device__ float g_a2[BATCH * 512];
__device__ float g_a3[BATCH * 128];

// ---------------- Laplace filter bank (parallel: one (c,k) per thread) ----------------
__global__ void k_filt(const float* __restrict__ la_a, const float* __restrict__ la_b) {
    int tid = threadIdx.x;
    if (tid >= CH * 16) return;
    int c = tid >> 4, k = tid & 15;
    const double A = 0.08, ep = 0.03, tal = 0.1;
    const double w = 6.283185307179586 * 50.0;
    const double coef = -ep / sqrt(1.0 - ep * ep);
    double ratio = (double)la_b[c] / (double)la_a[c];
    double t = (double)k / 15.0;
    double arg = w * (t - ratio - tal);
    g_filt[c * 16 + k] = (float)(A * exp(coef * arg) * (-sin(arg)));
}

// ---------------- x row statistics: sum + autocorrelation lags 0..15 (R6 version) ----------------
__global__ __launch_bounds__(256) void k_xstats(const float* __restrict__ x) {
    __shared__ float xs[LIN + 16];
    __shared__ float part[8][17];
    int b = blockIdx.x, tid = threadIdx.x;
    int warp = tid >> 5, lane = tid & 31;
    for (int i = tid; i < LIN; i += 256) xs[i] = x[b * LIN + i];
    if (tid < 16) xs[LIN + tid] = 0.f;
    __syncthreads();
    float acc[16];
#pragma unroll
    for (int d = 0; d < 16; d++) acc[d] = 0.f;
    float s = 0.f;
    for (int i = tid; i < LIN; i += 256) {
        float xi = xs[i];
        s += xi;
#pragma unroll
        for (int d = 0; d < 16; d++) acc[d] = fmaf(xi, xs[i + d], acc[d]);
    }
#pragma unroll
    for (int off = 16; off > 0; off >>= 1) {
        s += __shfl_down_sync(0xffffffffu, s, off);
#pragma unroll
        for (int d = 0; d < 16; d++)
            acc[d] += __shfl_down_sync(0xffffffffu, acc[d], off);
    }
    if (lane == 0) {
#pragma unroll
        for (int d = 0; d < 16; d++) part[warp][d] = acc[d];
        part[warp][16] = s;
    }
    __syncthreads();
    if (tid < 17) {
        float t = 0.f;
#pragma unroll
        for (int w = 0; w < 8; w++) t += part[w][tid];
        g_xpart[b * 17 + tid] = t;
    }
}

// ---------------- fused reduction + BN1 affine (single block, 544 threads) ----------------
__global__ __launch_bounds__(544) void k_redbn1(const float* __restrict__ la_bias,
                                                const float* __restrict__ g1,
                                                const float* __restrict__ b1) {
    __shared__ double Rs[17];
    int tid = threadIdx.x, warp = tid >> 5, lane = tid & 31;
    if (warp < 17) {
        double s = 0;
        for (int b = lane; b < BATCH; b += 32) s += (double)g_xpart[b * 17 + warp];
#pragma unroll
        for (int off = 16; off > 0; off >>= 1)
            s += __shfl_down_sync(0xffffffffu, s, off);
        if (lane == 0) Rs[warp] = s;
    }
    __syncthreads();
    if (tid < CH * 16) {
        int c = tid >> 4, k = tid & 15;
        double fk = (double)g_filt[c * 16 + k];
        double q = 0;
#pragma unroll
        for (int k2 = 0; k2 < 16; k2++) {
            int d = k2 - k; if (d < 0) d = -d;
            q += (double)g_filt[c * 16 + k2] * Rs[d];
        }
        q *= fk;
        double F1p = fk;
#pragma unroll
        for (int off = 8; off > 0; off >>= 1) {
            q += __shfl_down_sync(0xffffffffu, q, off, 16);
            F1p += __shfl_down_sync(0xffffffffu, F1p, off, 16);
        }
        if (k == 0) {
            double S = Rs[16];
            double N = (double)BATCH * (double)LCONV;
            double Ey = F1p * S / N;
            double var = q / N - Ey * Ey;
            double mean = (double)la_bias[c] + Ey;
            double inv = 1.0 / sqrt(var + 1e-5);
            double sc = (double)g1[c] * inv;
            g_bn1_sc3[c] = (float)(sc / 3.0);
            g_bn1_sh[c] = (float)((double)b1[c] - mean * sc);
        }
    }
}

// ---------------- pass 2: fused conv+BN+avgpool -> register-resident branches ----------------
#define HPAD 556
__global__ __launch_bounds__(256) void k_branch(
    const float* __restrict__ x, const float* __restrict__ la_bias,
    const float* __restrict__ a1_w, const float* __restrict__ a1_b,
    const float* __restrict__ e1_w, const float* __restrict__ e1_b,
    const float* __restrict__ f1_w, const float* __restrict__ f1_b,
    const float* __restrict__ fa_w, const float* __restrict__ fa_b) {
    __shared__ __align__(16) float xsg[130 * 28];
    __shared__ float hw[8][HPAD];
    int b = blockIdx.x, tid = threadIdx.x;
    int warp = tid >> 5, lane = tid & 31;
    const float* xr = x + b * LIN;

    for (int idx = tid; idx < 130 * 24; idx += 256) {
        int g = idx / 24, j = idx - g * 24;
        int pos = 8 * g + j;
        xsg[g * 28 + j] = (pos >= 16 && pos < 16 + LIN) ? xr[pos - 16] : 0.f;
    }
    __syncthreads();

    float* h = hw[warp];

    for (int cg = 0; cg < 4; cg++) {
        int c = warp + 8 * cg;
        float fw[16];
#pragma unroll
        for (int k = 0; k < 16; k++) fw[k] = g_filt[c * 16 + k];
        float cw[18];
#pragma unroll
        for (int j = 0; j < 18; j++) {
            float s = 0.f;
#pragma unroll
            for (int p = 0; p < 3; p++) {
                int k = j - p;
                if (k >= 0 && k < 16) s += fw[k];
            }
            cw[j] = s;
        }
        float sc3 = g_bn1_sc3[c];
        float sh2 = fmaf(3.f * la_bias[c], sc3, g_bn1_sh[c]);

        for (int g = lane; g < 130; g += 32) {
            const float4* p4 = (const float4*)&xsg[g * 28];
            float r[24];
#pragma unroll
            for (int w = 0; w < 6; w++) {
                float4 q = p4[w];
                r[4 * w] = q.x; r[4 * w + 1] = q.y; r[4 * w + 2] = q.z; r[4 * w + 3] = q.w;
            }
            int base = 4 * g + (g >> 2);
#pragma unroll
            for (int d = 0; d < 4; d++) {
                float s = 0.f;
#pragma unroll
                for (int j = 0; j < 18; j++) s = fmaf(r[2 * d + j], cw[j], s);
                h[base + d] = fmaf(s, sc3, sh2);
            }
        }
        __syncwarp();

        float mvA = 0.f, mvB = 0.f;
        if (lane < 31) {
            int hb = 17 * lane;
            float hr[34];
#pragma unroll
            for (int j = 0; j < 34; j++) hr[j] = h[hb + j + (j >> 4)];

            {
                float w8[8];
#pragma unroll
                for (int k = 0; k < 8; k++) w8[k] = a1_w[c * 8 + k];
                float wsum = 0.f;
#pragma unroll
                for (int k = 0; k < 8; k++) wsum += w8[k];
                float wbA = a1_b[c] - wsum;
                float ua[14];
#pragma unroll
                for (int i = 0; i < 14; i++) {
                    float a = wbA;
#pragma unroll
                    for (int k = 0; k < 8; k++) a = fmaf(hr[2 * i + k], w8[k], a);
                    ua[i] = fmaxf(a, 0.f);
                }
                float wE[8];
#pragma unroll
                for (int k = 0; k < 8; k++) wE[k] = e1_w[c * 8 + k];
                float wbE = 1.f - e1_b[c];
#pragma unroll
                for (int j = 0; j < 4; j++) {
                    float a = wbE;
#pragma unroll
                    for (int k = 0; k < 8; k++) a = fmaf(ua[2 * j + k], wE[k], a);
                    mvA = fmaxf(mvA, a);
                }
                g_x1pre[(b * CH + c) * 31 + lane] = mvA;
            }
            {
                float w8[8];
#pragma unroll
                for (int k = 0; k < 8; k++) w8[k] = f1_w[c * 8 + k];
                float wbF = 1.f - f1_b[c];
                float ub[14];
#pragma unroll
                for (int i = 0; i < 14; i++) {
                    float a = wbF;
#pragma unroll
                    for (int k = 0; k < 8; k++) a = fmaf(hr[2 * i + k], w8[k], a);
                    ub[i] = fmaxf(a, 0.f);
                }
                float wA[8];
#pragma unroll
                for (int k = 0; k < 8; k++) wA[k] = fa_w[c * 8 + k];
                float wsum = 0.f;
#pragma unroll
                for (int k = 0; k < 8; k++) wsum += wA[k];
                float wbA2 = fa_b[c] - wsum;
#pragma unroll
                for (int j = 0; j < 4; j++) {
                    float a = wbA2;
#pragma unroll
                    for (int k = 0; k < 8; k++) a = fmaf(ub[2 * j + k], wA[k], a);
                    mvB = fmaxf(mvB, a);
                }
                g_x2pre[(b * CH + c) * 31 + lane] = mvB;
            }
        }
        float sA = mvA, qA = mvA * mvA, sB = mvB, qB = mvB * mvB;
#pragma unroll
        for (int off = 16; off > 0; off >>= 1) {
            sA += __shfl_down_sync(0xffffffffu, sA, off);
            qA += __shfl_down_sync(0xffffffffu, qA, off);
            sB += __shfl_down_sync(0xffffffffu, sB, off);
            qB += __shfl_down_sync(0xffffffffu, qB, off);
        }
        if (lane == 0) {
            g_p2s[b * CH + c] = sA; g_p2q[b * CH + c] = qA;
            g_p3s[b * CH + c] = sB; g_p3q[b * CH + c] = qB;
        }
        __syncwarp();
    }
}

// ---------------- finalize BN2 / BN3 affine ----------------
__global__ void k_bn23(const float* __restrict__ g2, const float* __restrict__ b2,
                       const float* __restrict__ g3, const float* __restrict__ b3) {
    int c = blockIdx.x, which = blockIdx.y, tid = threadIdx.x;
    const float* ps = which ? g_p3s : g_p2s;
    const float* pq = which ? g_p3q : g_p2q;
    __shared__ double ss[128], sq[128];
    double s = 0, q = 0;
    for (int b = tid; b < BATCH; b += 128) {
        s += (double)ps[b * CH + c];
        q += (double)pq[b * CH + c];
    }
    ss[tid] = s; sq[tid] = q; __syncthreads();
    for (int o = 64; o > 0; o >>= 1) {
        if (tid < o) { ss[tid] += ss[tid + o]; sq[tid] += sq[tid + o]; }
        __syncthreads();
    }
    if (tid == 0) {
        double N = (double)BATCH * 31.0;
        double mean = ss[0] / N;
        double var = sq[0] / N - mean * mean;
        double inv = 1.0 / sqrt(var + 1e-5);
        double gg = which ? (double)g3[c] : (double)g2[c];
        double bb = which ? (double)b3[c] : (double)b2[c];
        double sc = gg * inv;
        if (which) { g_bn3_sc[c] = (float)sc; g_bn3_sh[c] = (float)(bb - mean * sc); }
        else       { g_bn2_sc[c] = (float)sc; g_bn2_sh[c] = (float)(bb - mean * sc); }
    }
}

// ---------------- BN + final eventually conv -> concat features z (B,768) ----------------
__global__ __launch_bounds__(128) void k_final(const float* __restrict__ e2_w,
                                               const float* __restrict__ e2_b,
                                               const float* __restrict__ f2_w,
                                               const float* __restrict__ f2_b) {
    int b = blockIdx.x;
    for (int idx = threadIdx.x; idx < 768; idx += 128) {
        int ct = idx / 12, j = idx % 12;
        int c = ct & 31;
        bool second = ct >= 32;
        const float* pre = (second ? g_x2pre : g_x1pre) + (b * CH + c) * 31 + 2 * j;
        const float* w = (second ? f2_w : e2_w) + c * 8;
        float base = 1.f - (second ? f2_b[c] : e2_b[c]);
        float sc = second ? g_bn3_sc[c] : g_bn2_sc[c];
        float shv = second ? g_bn3_sh[c] : g_bn2_sh[c];
        float sw = 0.f, dot = 0.f;
#pragma unroll
        for (int k = 0; k < 8; k++) { sw += w[k]; dot = fmaf(pre[k], w[k], dot); }
        float val = base + shv * sw + sc * dot;
        g_z[b * 768 + idx] = fmaxf(val, 0.f);
    }
}

// ---------------- SGEMM (R4-proven): register double-buffered, 64 threads ----------------
template <int BM, int TM>
__global__ __launch_bounds__(64) void sgemm_relu(const float* __restrict__ A,
                                                 const float* __restrict__ B,
                                                 const float* __restrict__ bias,
                                                 float* __restrict__ C,
                                                 int M, int N, int K) {
    constexpr int BK = 8;
    constexpr int LPT = (BM * BK / 4) / 64;
    const int tid = threadIdx.x;
    const int tx = tid & 7;
    const int ty = tid >> 3;
    const int m0 = blockIdx.y * BM;
    const int n0 = blockIdx.x * BM;
    __shared__ float As[BK][BM];
    __shared__ float Bs[BK][BM];
    float acc[TM][TM];
#pragma unroll
    for (int i = 0; i < TM; i++)
#pragma unroll
        for (int j = 0; j < TM; j++) acc[i][j] = 0.f;

    float4 pa[LPT], pb[LPT];
    const int nt = K / BK;

    auto loadG = [&](int t) {
        int k0 = t * BK;
#pragma unroll
        for (int L = 0; L < LPT; L++) {
            int i = tid + L * 64;
            int ar = i >> 1, ag = i & 1;
            pa[L] = *(const float4*)(A + (size_t)(m0 + ar) * K + k0 + ag * 4);
            int bk = i / (BM / 4), bc = i % (BM / 4);
            pb[L] = *(const float4*)(B + (size_t)(k0 + bk) * N + n0 + bc * 4);
        }
    };
    auto storeS = [&]() {
#pragma unroll
        for (int L = 0; L < LPT; L++) {
            int i = tid + L * 64;
            int ar = i >> 1, ag = i & 1;
            As[ag * 4 + 0][ar] = pa[L].x; As[ag * 4 + 1][ar] = pa[L].y;
            As[ag * 4 + 2][ar] = pa[L].z; As[ag * 4 + 3][ar] = pa[L].w;
            int bk = i / (BM / 4), bc = i % (BM / 4);
            *(float4*)(&Bs[bk][bc * 4]) = pb[L];
        }
    };

    loadG(0); storeS(); __syncthreads();
    for (int t = 0; t < nt; t++) {
        if (t + 1 < nt) loadG(t + 1);
#pragma unroll
        for (int kk = 0; kk < BK; kk++) {
            float af[TM], bf[TM];
#pragma unroll
            for (int i = 0; i < TM; i += 4) {
                float4 qa = *(const float4*)(&As[kk][ty * TM + i]);
                af[i] = qa.x; af[i + 1] = qa.y; af[i + 2] = qa.z; af[i + 3] = qa.w;
            }
#pragma unroll
            for (int j = 0; j < TM; j += 4) {
                float4 qb = *(const float4*)(&Bs[kk][tx * TM + j]);
                bf[j] = qb.x; bf[j + 1] = qb.y; bf[j + 2] = qb.z; bf[j + 3] = qb.w;
            }
#pragma unroll
            for (int i = 0; i < TM; i++)
#pragma unroll
                for (int j = 0; j < TM; j++) acc[i][j] = fmaf(af[i], bf[j], acc[i][j]);
        }
        __syncthreads();
        if (t + 1 < nt) { storeS(); __syncthreads(); }
    }
#pragma unroll
    for (int i = 0; i < TM; i++) {
        int m = m0 + ty * TM + i;
#pragma unroll
        for (int j = 0; j < TM; j += 4) {
            int n = n0 + tx * TM + j;
            float4 o;
            o.x = fmaxf(acc[i][j] + bias[n], 0.f);
            o.y = fmaxf(acc[i][j + 1] + bias[n + 1], 0.f);
            o.z = fmaxf(acc[i][j + 2] + bias[n + 2], 0.f);
            o.w = fmaxf(acc[i][j + 3] + bias[n + 3], 0.f);
            *(float4*)(C + (size_t)m * N + n) = o;
        }
    }
}

// ---------------- last tiny FC: (1024,128)@(128,10)+b, relu ----------------
__global__ void k_fc4(const float* __restrict__ w4, const float* __restrict__ b4,
                      float* __restrict__ out) {
    int idx = blockIdx.x * blockDim.x + threadIdx.x;
    if (idx >= BATCH * 10) return;
    int b = idx / 10, n = idx - b * 10;
    const float* a = g_a3 + b * 128;
    float acc = b4[n];
#pragma unroll 8
    for (int k = 0; k < 128; k++) acc = fmaf(a[k], w4[k * 10 + n], acc);
    out[idx] = fmaxf(acc, 0.f);
}

// ---------------- launch ----------------
extern "C" void kernel_launch(void* const* d_in, const int* in_sizes, int n_in,
                              void* d_out, int out_size) {
    const float* x       = (const float*)d_in[0];
    const float* la_a    = (const float*)d_in[1];
    const float* la_b    = (const float*)d_in[2];
    const float* la_bias = (const float*)d_in[3];
    const float* bn1_g   = (const float*)d_in[4];
    const float* bn1_b   = (const float*)d_in[5];
    const float* a1_w    = (const float*)d_in[6];
    const float* a1_b    = (const float*)d_in[7];
    const float* e1_w    = (const float*)d_in[8];
    const float* e1_b    = (const float*)d_in[9];
    const float* bn2_g   = (const float*)d_in[10];
    const float* bn2_b   = (const float*)d_in[11];
    const float* e2_w    = (const float*)d_in[12];
    const float* e2_b    = (const float*)d_in[13];
    const float* f1_w    = (const float*)d_in[14];
    const float* f1_b    = (const float*)d_in[15];
    const float* fa_w    = (const float*)d_in[16];
    const float* fa_b    = (const float*)d_in[17];
    const float* bn3_g   = (const float*)d_in[18];
    const float* bn3_b   = (const float*)d_in[19];
    const float* f2_w    = (const float*)d_in[20];
    const float* f2_b    = (const float*)d_in[21];
    const float* w1 = (const float*)d_in[22]; const float* b1 = (const float*)d_in[23];
    const float* w2 = (const float*)d_in[24]; const float* b2 = (const float*)d_in[25];
    const float* w3 = (const float*)d_in[26]; const float* b3 = (const float*)d_in[27];
    const float* w4 = (const float*)d_in[28]; const float* b4 = (const float*)d_in[29];
    float* out = (float*)d_out;

    float *p_z = nullptr, *p_a1 = nullptr, *p_a2 = nullptr, *p_a3 = nullptr;
    cudaGetSymbolAddress((void**)&p_z, g_z);
    cudaGetSymbolAddress((void**)&p_a1, g_a1);
    cudaGetSymbolAddress((void**)&p_a2, g_a2);
    cudaGetSymbolAddress((void**)&p_a3, g_a3);

    k_filt<<<1, 512>>>(la_a, la_b);
    k_xstats<<<BATCH, 256>>>(x);
    k_redbn1<<<1, 544>>>(la_bias, bn1_g, bn1_b);
    k_branch<<<BATCH, 256>>>(x, la_bias, a1_w, a1_b, e1_w, e1_b,
                             f1_w, f1_b, fa_w, fa_b);
    k_bn23<<<dim3(CH, 2), 128>>>(bn2_g, bn2_b, bn3_g, bn3_b);
    k_final<<<BATCH, 128>>>(e2_w, e2_b, f2_w, f2_b);
    sgemm_relu<64, 8><<<dim3(1024 / 64, 1024 / 64), 64>>>(p_z, w1, b1, p_a1, 1024, 1024, 768);
    sgemm_relu<64, 8><<<dim3(512 / 64, 1024 / 64), 64>>>(p_a1, w2, b2, p_a2, 1024, 512, 1024);
    sgemm_relu<32, 4><<<dim3(128 / 32, 1024 / 32), 64>>>(p_a2, w3, b3, p_a3, 1024, 128, 512);
    k_fc4<<<(BATCH * 10 + 127) / 128, 128>>>(w4, b4, out);
}

// round 11
// speedup vs baseline: 1.1319x; 1.0069x over previous
#include <cuda_runtime.h>
#include <math.h>

#define BATCH 1024
#define CH 32
#define LIN 1024
#define LCONV 1041
#define LH 520

// ---------------- scratch (device globals; no allocation) ----------------
__device__ float g_filt[CH * 16];
__device__ float g_xpart[BATCH * 17];     // per-row partial: lags 0..15, row-sum at 16
__device__ float g_bn1_sc3[CH];
__device__ float g_bn1_sh[CH];
__device__ float g_x1pre[BATCH * CH * 31];
__device__ float g_x2pre[BATCH * CH * 31];
__device__ float g_p2s[BATCH * CH];
__device__ float g_p2q[BATCH * CH];
__device__ float g_p3s[BATCH * CH];
__device__ float g_p3q[BATCH * CH];
__device__ float g_bn2_sc[CH], g_bn2_sh[CH], g_bn3_sc[CH], g_bn3_sh[CH];
__device__ float g_z[BATCH * 768];
__device__ float g_a1[BATCH * 1024];
__device__ float g_a2[BATCH * 512];
__device__ float g_a3[BATCH * 128];

// ---------------- Laplace filter bank (parallel: one (c,k) per thread) ----------------
__global__ void k_filt(const float* __restrict__ la_a, const float* __restrict__ la_b) {
    int tid = threadIdx.x;
    if (tid >= CH * 16) return;
    int c = tid >> 4, k = tid & 15;
    const double A = 0.08, ep = 0.03, tal = 0.1;
    const double w = 6.283185307179586 * 50.0;
    const double coef = -ep / sqrt(1.0 - ep * ep);
    double ratio = (double)la_b[c] / (double)la_a[c];
    double t = (double)k / 15.0;
    double arg = w * (t - ratio - tal);
    g_filt[c * 16 + k] = (float)(A * exp(coef * arg) * (-sin(arg)));
}

// ---------------- x row statistics: sum + autocorrelation lags 0..15 ----------------
__global__ __launch_bounds__(256) void k_xstats(const float* __restrict__ x) {
    __shared__ float xs[LIN + 16];
    __shared__ float part[8][17];
    int b = blockIdx.x, tid = threadIdx.x;
    int warp = tid >> 5, lane = tid & 31;
    for (int i = tid; i < LIN; i += 256) xs[i] = x[b * LIN + i];
    if (tid < 16) xs[LIN + tid] = 0.f;
    __syncthreads();
    float acc[16];
#pragma unroll
    for (int d = 0; d < 16; d++) acc[d] = 0.f;
    float s = 0.f;
    for (int i = tid; i < LIN; i += 256) {
        float xi = xs[i];
        s += xi;
#pragma unroll
        for (int d = 0; d < 16; d++) acc[d] = fmaf(xi, xs[i + d], acc[d]);
    }
#pragma unroll
    for (int off = 16; off > 0; off >>= 1) {
        s += __shfl_down_sync(0xffffffffu, s, off);
#pragma unroll
        for (int d = 0; d < 16; d++)
            acc[d] += __shfl_down_sync(0xffffffffu, acc[d], off);
    }
    if (lane == 0) {
#pragma unroll
        for (int d = 0; d < 16; d++) part[warp][d] = acc[d];
        part[warp][16] = s;
    }
    __syncthreads();
    if (tid < 17) {
        float t = 0.f;
#pragma unroll
        for (int w = 0; w < 8; w++) t += part[w][tid];
        g_xpart[b * 17 + tid] = t;
    }
}

// ---------------- fused reduction + BN1 affine (single block, 544 threads) ----------------
__global__ __launch_bounds__(544) void k_redbn1(const float* __restrict__ la_bias,
                                                const float* __restrict__ g1,
                                                const float* __restrict__ b1) {
    __shared__ double Rs[17];
    int tid = threadIdx.x, warp = tid >> 5, lane = tid & 31;
    if (warp < 17) {
        double s = 0;
        for (int b = lane; b < BATCH; b += 32) s += (double)g_xpart[b * 17 + warp];
#pragma unroll
        for (int off = 16; off > 0; off >>= 1)
            s += __shfl_down_sync(0xffffffffu, s, off);
        if (lane == 0) Rs[warp] = s;
    }
    __syncthreads();
    if (tid < CH * 16) {
        int c = tid >> 4, k = tid & 15;
        double fk = (double)g_filt[c * 16 + k];
        double q = 0;
#pragma unroll
        for (int k2 = 0; k2 < 16; k2++) {
            int d = k2 - k; if (d < 0) d = -d;
            q += (double)g_filt[c * 16 + k2] * Rs[d];
        }
        q *= fk;
        double F1p = fk;
#pragma unroll
        for (int off = 8; off > 0; off >>= 1) {
            q += __shfl_down_sync(0xffffffffu, q, off, 16);
            F1p += __shfl_down_sync(0xffffffffu, F1p, off, 16);
        }
        if (k == 0) {
            double S = Rs[16];
            double N = (double)BATCH * (double)LCONV;
            double Ey = F1p * S / N;
            double var = q / N - Ey * Ey;
            double mean = (double)la_bias[c] + Ey;
            double inv = 1.0 / sqrt(var + 1e-5);
            double sc = (double)g1[c] * inv;
            g_bn1_sc3[c] = (float)(sc / 3.0);
            g_bn1_sh[c] = (float)((double)b1[c] - mean * sc);
        }
    }
}

// ---------------- pass 2: fused conv+BN+avgpool -> register-resident branches ----------------
#define HPAD 556
__global__ __launch_bounds__(256) void k_branch(
    const float* __restrict__ x, const float* __restrict__ la_bias,
    const float* __restrict__ a1_w, const float* __restrict__ a1_b,
    const float* __restrict__ e1_w, const float* __restrict__ e1_b,
    const float* __restrict__ f1_w, const float* __restrict__ f1_b,
    const float* __restrict__ fa_w, const float* __restrict__ fa_b) {
    __shared__ __align__(16) float xsg[130 * 28];
    __shared__ float hw[8][HPAD];
    int b = blockIdx.x, tid = threadIdx.x;
    int warp = tid >> 5, lane = tid & 31;
    const float* xr = x + b * LIN;

    for (int idx = tid; idx < 130 * 24; idx += 256) {
        int g = idx / 24, j = idx - g * 24;
        int pos = 8 * g + j;
        xsg[g * 28 + j] = (pos >= 16 && pos < 16 + LIN) ? xr[pos - 16] : 0.f;
    }
    __syncthreads();

    float* h = hw[warp];

    for (int cg = 0; cg < 4; cg++) {
        int c = warp + 8 * cg;
        float fw[16];
#pragma unroll
        for (int k = 0; k < 16; k++) fw[k] = g_filt[c * 16 + k];
        float cw[18];
#pragma unroll
        for (int j = 0; j < 18; j++) {
            float s = 0.f;
#pragma unroll
            for (int p = 0; p < 3; p++) {
                int k = j - p;
                if (k >= 0 && k < 16) s += fw[k];
            }
            cw[j] = s;
        }
        float sc3 = g_bn1_sc3[c];
        float sh2 = fmaf(3.f * la_bias[c], sc3, g_bn1_sh[c]);

        for (int g = lane; g < 130; g += 32) {
            const float4* p4 = (const float4*)&xsg[g * 28];
            float r[24];
#pragma unroll
            for (int w = 0; w < 6; w++) {
                float4 q = p4[w];
                r[4 * w] = q.x; r[4 * w + 1] = q.y; r[4 * w + 2] = q.z; r[4 * w + 3] = q.w;
            }
            int base = 4 * g + (g >> 2);
#pragma unroll
            for (int d = 0; d < 4; d++) {
                float s = 0.f;
#pragma unroll
                for (int j = 0; j < 18; j++) s = fmaf(r[2 * d + j], cw[j], s);
                h[base + d] = fmaf(s, sc3, sh2);
            }
        }
        __syncwarp();

        float mvA = 0.f, mvB = 0.f;
        if (lane < 31) {
            int hb = 17 * lane;
            float hr[34];
#pragma unroll
            for (int j = 0; j < 34; j++) hr[j] = h[hb + j + (j >> 4)];

            {
                float w8[8];
#pragma unroll
                for (int k = 0; k < 8; k++) w8[k] = a1_w[c * 8 + k];
                float wsum = 0.f;
#pragma unroll
                for (int k = 0; k < 8; k++) wsum += w8[k];
                float wbA = a1_b[c] - wsum;
                float ua[14];
#pragma unroll
                for (int i = 0; i < 14; i++) {
                    float a = wbA;
#pragma unroll
                    for (int k = 0; k < 8; k++) a = fmaf(hr[2 * i + k], w8[k], a);
                    ua[i] = fmaxf(a, 0.f);
                }
                float wE[8];
#pragma unroll
                for (int k = 0; k < 8; k++) wE[k] = e1_w[c * 8 + k];
                float wbE = 1.f - e1_b[c];
#pragma unroll
                for (int j = 0; j < 4; j++) {
                    float a = wbE;
#pragma unroll
                    for (int k = 0; k < 8; k++) a = fmaf(ua[2 * j + k], wE[k], a);
                    mvA = fmaxf(mvA, a);
                }
                g_x1pre[(b * CH + c) * 31 + lane] = mvA;
            }
            {
                float w8[8];
#pragma unroll
                for (int k = 0; k < 8; k++) w8[k] = f1_w[c * 8 + k];
                float wbF = 1.f - f1_b[c];
                float ub[14];
#pragma unroll
                for (int i = 0; i < 14; i++) {
                    float a = wbF;
#pragma unroll
                    for (int k = 0; k < 8; k++) a = fmaf(hr[2 * i + k], w8[k], a);
                    ub[i] = fmaxf(a, 0.f);
                }
                float wA[8];
#pragma unroll
                for (int k = 0; k < 8; k++) wA[k] = fa_w[c * 8 + k];
                float wsum = 0.f;
#pragma unroll
                for (int k = 0; k < 8; k++) wsum += wA[k];
                float wbA2 = fa_b[c] - wsum;
#pragma unroll
                for (int j = 0; j < 4; j++) {
                    float a = wbA2;
#pragma unroll
                    for (int k = 0; k < 8; k++) a = fmaf(ub[2 * j + k], wA[k], a);
                    mvB = fmaxf(mvB, a);
                }
                g_x2pre[(b * CH + c) * 31 + lane] = mvB;
            }
        }
        float sA = mvA, qA = mvA * mvA, sB = mvB, qB = mvB * mvB;
#pragma unroll
        for (int off = 16; off > 0; off >>= 1) {
            sA += __shfl_down_sync(0xffffffffu, sA, off);
            qA += __shfl_down_sync(0xffffffffu, qA, off);
            sB += __shfl_down_sync(0xffffffffu, sB, off);
            qB += __shfl_down_sync(0xffffffffu, qB, off);
        }
        if (lane == 0) {
            g_p2s[b * CH + c] = sA; g_p2q[b * CH + c] = qA;
            g_p3s[b * CH + c] = sB; g_p3q[b * CH + c] = qB;
        }
        __syncwarp();
    }
}

// ---------------- finalize BN2 / BN3 affine ----------------
__global__ void k_bn23(const float* __restrict__ g2, const float* __restrict__ b2,
                       const float* __restrict__ g3, const float* __restrict__ b3) {
    int c = blockIdx.x, which = blockIdx.y, tid = threadIdx.x;
    const float* ps = which ? g_p3s : g_p2s;
    const float* pq = which ? g_p3q : g_p2q;
    __shared__ double ss[128], sq[128];
    double s = 0, q = 0;
    for (int b = tid; b < BATCH; b += 128) {
        s += (double)ps[b * CH + c];
        q += (double)pq[b * CH + c];
    }
    ss[tid] = s; sq[tid] = q; __syncthreads();
    for (int o = 64; o > 0; o >>= 1) {
        if (tid < o) { ss[tid] += ss[tid + o]; sq[tid] += sq[tid + o]; }
        __syncthreads();
    }
    if (tid == 0) {
        double N = (double)BATCH * 31.0;
        double mean = ss[0] / N;
        double var = sq[0] / N - mean * mean;
        double inv = 1.0 / sqrt(var + 1e-5);
        double gg = which ? (double)g3[c] : (double)g2[c];
        double bb = which ? (double)b3[c] : (double)b2[c];
        double sc = gg * inv;
        if (which) { g_bn3_sc[c] = (float)sc; g_bn3_sh[c] = (float)(bb - mean * sc); }
        else       { g_bn2_sc[c] = (float)sc; g_bn2_sh[c] = (float)(bb - mean * sc); }
    }
}

// ---------------- BN + final eventually conv -> concat features z (B,768) ----------------
__global__ __launch_bounds__(128) void k_final(const float* __restrict__ e2_w,
                                               const float* __restrict__ e2_b,
                                               const float* __restrict__ f2_w,
                                               const float* __restrict__ f2_b) {
    int b = blockIdx.x;
    for (int idx = threadIdx.x; idx < 768; idx += 128) {
        int ct = idx / 12, j = idx % 12;
        int c = ct & 31;
        bool second = ct >= 32;
        const float* pre = (second ? g_x2pre : g_x1pre) + (b * CH + c) * 31 + 2 * j;
        const float* w = (second ? f2_w : e2_w) + c * 8;
        float base = 1.f - (second ? f2_b[c] : e2_b[c]);
        float sc = second ? g_bn3_sc[c] : g_bn2_sc[c];
        float shv = second ? g_bn3_sh[c] : g_bn2_sh[c];
        float sw = 0.f, dot = 0.f;
#pragma unroll
        for (int k = 0; k < 8; k++) { sw += w[k]; dot = fmaf(pre[k], w[k], dot); }
        float val = base + shv * sw + sc * dot;
        g_z[b * 768 + idx] = fmaxf(val, 0.f);
    }
}

// ---------------- SGEMM 128 threads, BM=BN=64, BK=16, 4x8 microtile ----------------
__global__ __launch_bounds__(128) void sgemm128(const float* __restrict__ A,
                                                const float* __restrict__ B,
                                                const float* __restrict__ bias,
                                                float* __restrict__ C,
                                                int M, int N, int K) {
    constexpr int BM = 64, BN = 64, BK = 16;
    const int tid = threadIdx.x;
    const int tx = tid & 7;    // 8 col groups * 8 = 64
    const int ty = tid >> 3;   // 16 row groups * 4 = 64
    const int m0 = blockIdx.y * BM;
    const int n0 = blockIdx.x * BN;
    __shared__ __align__(16) float As[BK][BM + 4];
    __shared__ __align__(16) float Bs[BK][BN + 4];
    float acc[4][8];
#pragma unroll
    for (int i = 0; i < 4; i++)
#pragma unroll
        for (int j = 0; j < 8; j++) acc[i][j] = 0.f;

    float4 pa[2], pb[2];
    const int nt = K / BK;

    auto loadG = [&](int t) {
        int k0 = t * BK;
#pragma unroll
        for (int L = 0; L < 2; L++) {
            int i = tid + L * 128;
            int ar = i >> 2, ac = i & 3;     // 64 rows x 4 col-groups
            pa[L] = *(const float4*)(A + (size_t)(m0 + ar) * K + k0 + ac * 4);
            int br = i >> 4, bc = i & 15;    // 16 rows x 16 col-groups
            pb[L] = *(const float4*)(B + (size_t)(k0 + br) * N + n0 + bc * 4);
        }
    };
    auto storeS = [&]() {
#pragma unroll
        for (int L = 0; L < 2; L++) {
            int i = tid + L * 128;
            int ar = i >> 2, ac = i & 3;
            As[ac * 4 + 0][ar] = pa[L].x; As[ac * 4 + 1][ar] = pa[L].y;
            As[ac * 4 + 2][ar] = pa[L].z; As[ac * 4 + 3][ar] = pa[L].w;
            int br = i >> 4, bc = i & 15;
            *(float4*)(&Bs[br][bc * 4]) = pb[L];
        }
    };

    loadG(0); storeS(); __syncthreads();
    for (int t = 0; t < nt; t++) {
        if (t + 1 < nt) loadG(t + 1);
#pragma unroll
        for (int kk = 0; kk < BK; kk++) {
            float4 qa = *(const float4*)(&As[kk][ty * 4]);
            float af[4] = {qa.x, qa.y, qa.z, qa.w};
            float bf[8];
#pragma unroll
            for (int j = 0; j < 8; j += 4) {
                float4 qb = *(const float4*)(&Bs[kk][tx * 8 + j]);
                bf[j] = qb.x; bf[j + 1] = qb.y; bf[j + 2] = qb.z; bf[j + 3] = qb.w;
            }
#pragma unroll
            for (int i = 0; i < 4; i++)
#pragma unroll
                for (int j = 0; j < 8; j++) acc[i][j] = fmaf(af[i], bf[j], acc[i][j]);
        }
        __syncthreads();
        if (t + 1 < nt) { storeS(); __syncthreads(); }
    }
#pragma unroll
    for (int i = 0; i < 4; i++) {
        int m = m0 + ty * 4 + i;
#pragma unroll
        for (int j = 0; j < 8; j += 4) {
            int n = n0 + tx * 8 + j;
            float4 o;
            o.x = fmaxf(acc[i][j] + bias[n], 0.f);
            o.y = fmaxf(acc[i][j + 1] + bias[n + 1], 0.f);
            o.z = fmaxf(acc[i][j + 2] + bias[n + 2], 0.f);
            o.w = fmaxf(acc[i][j + 3] + bias[n + 3], 0.f);
            *(float4*)(C + (size_t)m * N + n) = o;
        }
    }
}

// ---------------- SGEMM small-N (32x32, 64 threads) for GEMM3 (R4-proven) ----------------
template <int BM, int TM>
__global__ __launch_bounds__(64) void sgemm_relu(const float* __restrict__ A,
                                                 const float* __restrict__ B,
                                                 const float* __restrict__ bias,
                                                 float* __restrict__ C,
                                                 int M, int N, int K) {
    constexpr int BK = 8;
    constexpr int LPT = (BM * BK / 4) / 64;
    const int tid = threadIdx.x;
    const int tx = tid & 7;
    const int ty = tid >> 3;
    const int m0 = blockIdx.y * BM;
    const int n0 = blockIdx.x * BM;
    __shared__ float As[BK][BM];
    __shared__ float Bs[BK][BM];
    float acc[TM][TM];
#pragma unroll
    for (int i = 0; i < TM; i++)
#pragma unroll
        for (int j = 0; j < TM; j++) acc[i][j] = 0.f;

    float4 pa[LPT], pb[LPT];
    const int nt = K / BK;

    auto loadG = [&](int t) {
        int k0 = t * BK;
#pragma unroll
        for (int L = 0; L < LPT; L++) {
            int i = tid + L * 64;
            int ar = i >> 1, ag = i & 1;
            pa[L] = *(const float4*)(A + (size_t)(m0 + ar) * K + k0 + ag * 4);
            int bk = i / (BM / 4), bc = i % (BM / 4);
            pb[L] = *(const float4*)(B + (size_t)(k0 + bk) * N + n0 + bc * 4);
        }
    };
    auto storeS = [&]() {
#pragma unroll
        for (int L = 0; L < LPT; L++) {
            int i = tid + L * 64;
            int ar = i >> 1, ag = i & 1;
            As[ag * 4 + 0][ar] = pa[L].x; As[ag * 4 + 1][ar] = pa[L].y;
            As[ag * 4 + 2][ar] = pa[L].z; As[ag * 4 + 3][ar] = pa[L].w;
            int bk = i / (BM / 4), bc = i % (BM / 4);
            *(float4*)(&Bs[bk][bc * 4]) = pb[L];
        }
    };

    loadG(0); storeS(); __syncthreads();
    for (int t = 0; t < nt; t++) {
        if (t + 1 < nt) loadG(t + 1);
#pragma unroll
        for (int kk = 0; kk < BK; kk++) {
            float af[TM], bf[TM];
#pragma unroll
            for (int i = 0; i < TM; i += 4) {
                float4 qa = *(const float4*)(&As[kk][ty * TM + i]);
                af[i] = qa.x; af[i + 1] = qa.y; af[i + 2] = qa.z; af[i + 3] = qa.w;
            }
#pragma unroll
            for (int j = 0; j < TM; j += 4) {
                float4 qb = *(const float4*)(&Bs[kk][tx * TM + j]);
                bf[j] = qb.x; bf[j + 1] = qb.y; bf[j + 2] = qb.z; bf[j + 3] = qb.w;
            }
#pragma unroll
            for (int i = 0; i < TM; i++)
#pragma unroll
                for (int j = 0; j < TM; j++) acc[i][j] = fmaf(af[i], bf[j], acc[i][j]);
        }
        __syncthreads();
        if (t + 1 < nt) { storeS(); __syncthreads(); }
    }
#pragma unroll
    for (int i = 0; i < TM; i++) {
        int m = m0 + ty * TM + i;
#pragma unroll
        for (int j = 0; j < TM; j += 4) {
            int n = n0 + tx * TM + j;
            float4 o;
            o.x = fmaxf(acc[i][j] + bias[n], 0.f);
            o.y = fmaxf(acc[i][j + 1] + bias[n + 1], 0.f);
            o.z = fmaxf(acc[i][j + 2] + bias[n + 2], 0.f);
            o.w = fmaxf(acc[i][j + 3] + bias[n + 3], 0.f);
            *(float4*)(C + (size_t)m * N + n) = o;
        }
    }
}

// ---------------- last tiny FC: (1024,128)@(128,10)+b, relu ----------------
__global__ void k_fc4(const float* __restrict__ w4, const float* __restrict__ b4,
                      float* __restrict__ out) {
    int idx = blockIdx.x * blockDim.x + threadIdx.x;
    if (idx >= BATCH * 10) return;
    int b = idx / 10, n = idx - b * 10;
    const float* a = g_a3 + b * 128;
    float acc = b4[n];
#pragma unroll 8
    for (int k = 0; k < 128; k++) acc = fmaf(a[k], w4[k * 10 + n], acc);
    out[idx] = fmaxf(acc, 0.f);
}

// ---------------- launch ----------------
extern "C" void kernel_launch(void* const* d_in, const int* in_sizes, int n_in,
                              void* d_out, int out_size) {
    const float* x       = (const float*)d_in[0];
    const float* la_a    = (const float*)d_in[1];
    const float* la_b    = (const float*)d_in[2];
    const float* la_bias = (const float*)d_in[3];
    const float* bn1_g   = (const float*)d_in[4];
    const float* bn1_b   = (const float*)d_in[5];
    const float* a1_w    = (const float*)d_in[6];
    const float* a1_b    = (const float*)d_in[7];
    const float* e1_w    = (const float*)d_in[8];
    const float* e1_b    = (const float*)d_in[9];
    const float* bn2_g   = (const float*)d_in[10];
    const float* bn2_b   = (const float*)d_in[11];
    const float* e2_w    = (const float*)d_in[12];
    const float* e2_b    = (const float*)d_in[13];
    const float* f1_w    = (const float*)d_in[14];
    const float* f1_b    = (const float*)d_in[15];
    const float* fa_w    = (const float*)d_in[16];
    const float* fa_b    = (const float*)d_in[17];
    const float* bn3_g   = (const float*)d_in[18];
    const float* bn3_b   = (const float*)d_in[19];
    const float* f2_w    = (const float*)d_in[20];
    const float* f2_b    = (const float*)d_in[21];
    const float* w1 = (const float*)d_in[22]; const float* b1 = (const float*)d_in[23];
    const float* w2 = (const float*)d_in[24]; const float* b2 = (const float*)d_in[25];
    const float* w3 = (const float*)d_in[26]; const float* b3 = (const float*)d_in[27];
    const float* w4 = (const float*)d_in[28]; const float* b4 = (const float*)d_in[29];
    float* out = (float*)d_out;

    float *p_z = nullptr, *p_a1 = nullptr, *p_a2 = nullptr, *p_a3 = nullptr;
    cudaGetSymbolAddress((void**)&p_z, g_z);
    cudaGetSymbolAddress((void**)&p_a1, g_a1);
    cudaGetSymbolAddress((void**)&p_a2, g_a2);
    cudaGetSymbolAddress((void**)&p_a3, g_a3);

    k_filt<<<1, 512>>>(la_a, la_b);
    k_xstats<<<BATCH, 256>>>(x);
    k_redbn1<<<1, 544>>>(la_bias, bn1_g, bn1_b);
    k_branch<<<BATCH, 256>>>(x, la_bias, a1_w, a1_b, e1_w, e1_b,
                             f1_w, f1_b, fa_w, fa_b);
    k_bn23<<<dim3(CH, 2), 128>>>(bn2_g, bn2_b, bn3_g, bn3_b);
    k_final<<<BATCH, 128>>>(e2_w, e2_b, f2_w, f2_b);
    sgemm128<<<dim3(1024 / 64, 1024 / 64), 128>>>(p_z, w1, b1, p_a1, 1024, 1024, 768);
    sgemm128<<<dim3(512 / 64, 1024 / 64), 128>>>(p_a1, w2, b2, p_a2, 1024, 512, 1024);
    sgemm_relu<32, 4><<<dim3(128 / 32, 1024 / 32), 64>>>(p_a2, w3, b3, p_a3, 1024, 128, 512);
    k_fc4<<<(BATCH * 10 + 127) / 128, 128>>>(w4, b4, out);
}